// round 15
// baseline (speedup 1.0000x reference)
#include <cuda_runtime.h>
#include <cuda_fp16.h>
#include <math.h>

#define NN 100000
#define NPAD 100032
#define EE 3200000
#define HIDC 128

// ---------------- device scratch (no allocations allowed) ----------------
__device__ int    g_flag64;
__device__ int    g_deg[NN];
__device__ float  g_dinv[NN];
__device__ int    g_rowptr[NN + 1];
__device__ int    g_cursor[NN];
__device__ int    g_src[EE];
__device__ float  g_w[EE];
__device__ float  g_h0[(size_t)NN * HIDC];
__device__ float  g_bufA[(size_t)NN * HIDC];
__device__ float  g_bufB[(size_t)NN * HIDC];
__device__ __half g_h16a[(size_t)NPAD * HIDC];   // fp16 gather tables (double buffer)
__device__ __half g_h16b[(size_t)NPAD * HIDC];

// ---------------- f32x2 packed math helpers (sm_10x FFMA2) ----------------
__device__ __forceinline__ unsigned long long pk2(float a, float b) {
    unsigned long long r;
    asm("mov.b64 %0, {%1, %2};" : "=l"(r) : "f"(a), "f"(b));
    return r;
}
__device__ __forceinline__ void upk2(unsigned long long v, float& a, float& b) {
    asm("mov.b64 {%0, %1}, %2;" : "=f"(a), "=f"(b) : "l"(v));
}
__device__ __forceinline__ void fma2(unsigned long long& d,
                                     unsigned long long a,
                                     unsigned long long b) {
    asm("fma.rn.f32x2 %0, %1, %2, %0;" : "+l"(d) : "l"(a), "l"(b));
}

// ---------------- dtype detection ----------------
__global__ void detect_kernel(const int* __restrict__ ew) {
    if (threadIdx.x == 0) {
        int allzero = 1;
        for (int i = 0; i < 256; i++) {
            if (ew[2 * i + 1] != 0) { allzero = 0; break; }
        }
        g_flag64 = allzero;
    }
}

__device__ __forceinline__ int load_idx(const int* __restrict__ ew, long long elem, int f64) {
    return f64 ? ew[2 * elem] : ew[elem];
}

// ---------------- graph build ----------------
__global__ void count_kernel(const int* __restrict__ ew) {
    int e = blockIdx.x * blockDim.x + threadIdx.x;
    if (e < EE) {
        int f64 = g_flag64;
        int c = load_idx(ew, (long long)EE + e, f64);
        if ((unsigned)c < NN) atomicAdd(&g_deg[c], 1);
    }
}

__global__ void scan_kernel() {
    __shared__ int sums[1024];
    const int T = 1024;
    int t = threadIdx.x;
    const int CH = (NN + T - 1) / T;
    int lo = t * CH;
    int hi = lo + CH;
    if (hi > NN) hi = NN;
    if (lo > NN) lo = NN;
    int s = 0;
    for (int i = lo; i < hi; i++) s += g_deg[i];
    sums[t] = s;
    __syncthreads();
    for (int off = 1; off < T; off <<= 1) {
        int v = (t >= off) ? sums[t - off] : 0;
        __syncthreads();
        sums[t] += v;
        __syncthreads();
    }
    int run = sums[t] - s;
    for (int i = lo; i < hi; i++) {
        int d = g_deg[i];
        g_rowptr[i] = run;
        g_cursor[i] = run;
        g_dinv[i]   = rsqrtf((float)(d + 1));
        run += d;
    }
    if (t == T - 1) g_rowptr[NN] = run;
}

__global__ void fill_kernel(const int* __restrict__ ew) {
    int e = blockIdx.x * blockDim.x + threadIdx.x;
    if (e < EE) {
        int f64 = g_flag64;
        int r = load_idx(ew, e, f64);
        int c = load_idx(ew, (long long)EE + e, f64);
        if ((unsigned)r < NN && (unsigned)c < NN) {
            int pos = atomicAdd(&g_cursor[c], 1);
            g_src[pos] = r;
            g_w[pos]   = g_dinv[r] * g_dinv[c];
        }
    }
}

// ---------------- FFMA2 GEMM (input projection): out = cs*S + cw*(S@W) ----------------
__global__ __launch_bounds__(256) void gemm_kernel(const float* __restrict__ S,
                                                   const float* __restrict__ W,
                                                   const float* __restrict__ bias,
                                                   float cs, float cw, int relu,
                                                   float* __restrict__ out,
                                                   __half* __restrict__ out16) {
    __shared__ float ss[64][132];
    __shared__ float Ws[32][128];
    int tid  = threadIdx.x;
    int warp = tid >> 5;
    int lane = tid & 31;
    int row0 = blockIdx.x * 64;
    int rbase = warp * 8;

    {
#pragma unroll
        for (int i = 0; i < 8; i++) {
            int idx = tid + i * 256;
            int r = idx >> 5, c4 = idx & 31;
            int gr = row0 + r;
            if (gr > NN - 1) gr = NN - 1;
            float4 v = *(const float4*)(S + (size_t)gr * HIDC + c4 * 4);
            *(float4*)&ss[r][c4 * 4] = v;
        }
    }

    unsigned long long acc[8][2];
#pragma unroll
    for (int r = 0; r < 8; r++) { acc[r][0] = 0ull; acc[r][1] = 0ull; }

    for (int kc = 0; kc < 4; kc++) {
        __syncthreads();
        const float4* Wv = (const float4*)(W + (size_t)kc * 32 * HIDC);
#pragma unroll
        for (int i = 0; i < 4; i++) {
            int idx = tid + i * 256;
            int r = idx >> 5, c4 = idx & 31;
            *(float4*)&Ws[r][c4 * 4] = Wv[r * 32 + c4];
        }
        __syncthreads();

#pragma unroll
        for (int kk4 = 0; kk4 < 8; kk4++) {
            unsigned long long wp[4][2];
#pragma unroll
            for (int t = 0; t < 4; t++) {
                float4 w4 = *(const float4*)&Ws[kk4 * 4 + t][lane * 4];
                wp[t][0] = pk2(w4.x, w4.y);
                wp[t][1] = pk2(w4.z, w4.w);
            }
#pragma unroll
            for (int r = 0; r < 8; r++) {
                float4 sv = *(const float4*)&ss[rbase + r][kc * 32 + kk4 * 4];
                unsigned long long s0 = pk2(sv.x, sv.x);
                unsigned long long s1 = pk2(sv.y, sv.y);
                unsigned long long s2 = pk2(sv.z, sv.z);
                unsigned long long s3 = pk2(sv.w, sv.w);
                fma2(acc[r][0], s0, wp[0][0]); fma2(acc[r][1], s0, wp[0][1]);
                fma2(acc[r][0], s1, wp[1][0]); fma2(acc[r][1], s1, wp[1][1]);
                fma2(acc[r][0], s2, wp[2][0]); fma2(acc[r][1], s2, wp[2][1]);
                fma2(acc[r][0], s3, wp[3][0]); fma2(acc[r][1], s3, wp[3][1]);
            }
        }
    }

    int col = lane * 4;
    float4 b4 = make_float4(0.f, 0.f, 0.f, 0.f);
    if (bias) b4 = *(const float4*)(bias + col);

#pragma unroll
    for (int r = 0; r < 8; r++) {
        int grow = row0 + rbase + r;
        if (grow >= NN) break;
        float4 o;
        upk2(acc[r][0], o.x, o.y);
        upk2(acc[r][1], o.z, o.w);
        o.x *= cw; o.y *= cw; o.z *= cw; o.w *= cw;
        if (cs != 0.f) {
            float4 sv = *(const float4*)&ss[rbase + r][col];
            o.x = fmaf(cs, sv.x, o.x);
            o.y = fmaf(cs, sv.y, o.y);
            o.z = fmaf(cs, sv.z, o.z);
            o.w = fmaf(cs, sv.w, o.w);
        }
        o.x += b4.x; o.y += b4.y; o.z += b4.z; o.w += b4.w;
        if (relu) {
            o.x = fmaxf(o.x, 0.f); o.y = fmaxf(o.y, 0.f);
            o.z = fmaxf(o.z, 0.f); o.w = fmaxf(o.w, 0.f);
        }
        *(float4*)(out + (size_t)grow * HIDC + col) = o;
        if (out16) {
            uint2 hp;
            *(__half2*)&hp.x = __floats2half2_rn(o.x, o.y);
            *(__half2*)&hp.y = __floats2half2_rn(o.z, o.w);
            *(uint2*)(out16 + (size_t)grow * HIDC + col) = hp;
        }
    }
}

// ---------------- FUSED layer: SpMM -> smem -> FFMA2 GEMM -> out ----------------
// out = cs*s + cw*(s@W), s = 0.9*(A_norm h) + 0.1*h0, ReLU. fp16 table out.
__global__ __launch_bounds__(256) void fused_kernel(const __half* __restrict__ h16,
                                                    const float* __restrict__ hf,
                                                    const float* __restrict__ h0f,
                                                    const float* __restrict__ W,
                                                    float cs, float cw,
                                                    float* __restrict__ out,
                                                    __half* __restrict__ out16) {
    __shared__ float ss[64][132];
    __shared__ float Ws[32][128];
    int tid  = threadIdx.x;
    int warp = tid >> 5;
    int lane = tid & 31;
    int row0 = blockIdx.x * 64;
    int rbase = warp * 8;

    // ---- phase 1: SpMM, warp computes rows rbase..rbase+7 into smem ----
    for (int r = 0; r < 8; r++) {
        int node = row0 + rbase + r;
        float4 o = make_float4(0.f, 0.f, 0.f, 0.f);
        if (node < NN) {
            int beg = g_rowptr[node];
            int end = g_rowptr[node + 1];
            float4 acc = make_float4(0.f, 0.f, 0.f, 0.f);
            int e0 = beg;
            for (; e0 + 32 <= end; e0 += 32) {
                int   src = g_src[e0 + lane];
                float w   = g_w[e0 + lane];
#pragma unroll 8
                for (int j = 0; j < 32; j++) {
                    int   sidx = __shfl_sync(0xffffffffu, src, j);
                    float ww   = __shfl_sync(0xffffffffu, w, j);
                    uint2 rv = *(const uint2*)(h16 + (size_t)sidx * HIDC + lane * 4);
                    float2 f0 = __half22float2(*(const __half2*)&rv.x);
                    float2 f1 = __half22float2(*(const __half2*)&rv.y);
                    acc.x = fmaf(ww, f0.x, acc.x);
                    acc.y = fmaf(ww, f0.y, acc.y);
                    acc.z = fmaf(ww, f1.x, acc.z);
                    acc.w = fmaf(ww, f1.y, acc.w);
                }
            }
            if (e0 < end) {
                int cnt = end - e0;
                int   src = 0;
                float w   = 0.f;
                if (lane < cnt) { src = g_src[e0 + lane]; w = g_w[e0 + lane]; }
                for (int j = 0; j < cnt; j++) {
                    int   sidx = __shfl_sync(0xffffffffu, src, j);
                    float ww   = __shfl_sync(0xffffffffu, w, j);
                    uint2 rv = *(const uint2*)(h16 + (size_t)sidx * HIDC + lane * 4);
                    float2 f0 = __half22float2(*(const __half2*)&rv.x);
                    float2 f1 = __half22float2(*(const __half2*)&rv.y);
                    acc.x = fmaf(ww, f0.x, acc.x);
                    acc.y = fmaf(ww, f0.y, acc.y);
                    acc.z = fmaf(ww, f1.x, acc.z);
                    acc.w = fmaf(ww, f1.y, acc.w);
                }
            }
            // self loop in fp32
            float di = g_dinv[node];
            float wsc = di * di;
            float4 hv = *(const float4*)(hf + (size_t)node * HIDC + lane * 4);
            acc.x = fmaf(wsc, hv.x, acc.x);
            acc.y = fmaf(wsc, hv.y, acc.y);
            acc.z = fmaf(wsc, hv.z, acc.z);
            acc.w = fmaf(wsc, hv.w, acc.w);

            float4 r0 = *(const float4*)(h0f + (size_t)node * HIDC + lane * 4);
            o.x = 0.9f * acc.x + 0.1f * r0.x;
            o.y = 0.9f * acc.y + 0.1f * r0.y;
            o.z = 0.9f * acc.z + 0.1f * r0.z;
            o.w = 0.9f * acc.w + 0.1f * r0.w;
        }
        *(float4*)&ss[rbase + r][lane * 4] = o;
    }

    // ---- phase 2: FFMA2 GEMM from smem s ----
    unsigned long long acc[8][2];
#pragma unroll
    for (int r = 0; r < 8; r++) { acc[r][0] = 0ull; acc[r][1] = 0ull; }

    for (int kc = 0; kc < 4; kc++) {
        __syncthreads();   // first iter: orders phase-1 writes; later: guards Ws reuse
        const float4* Wv = (const float4*)(W + (size_t)kc * 32 * HIDC);
#pragma unroll
        for (int i = 0; i < 4; i++) {
            int idx = tid + i * 256;
            int r = idx >> 5, c4 = idx & 31;
            *(float4*)&Ws[r][c4 * 4] = Wv[r * 32 + c4];
        }
        __syncthreads();

#pragma unroll
        for (int kk4 = 0; kk4 < 8; kk4++) {
            unsigned long long wp[4][2];
#pragma unroll
            for (int t = 0; t < 4; t++) {
                float4 w4 = *(const float4*)&Ws[kk4 * 4 + t][lane * 4];
                wp[t][0] = pk2(w4.x, w4.y);
                wp[t][1] = pk2(w4.z, w4.w);
            }
#pragma unroll
            for (int r = 0; r < 8; r++) {
                float4 sv = *(const float4*)&ss[rbase + r][kc * 32 + kk4 * 4];
                unsigned long long s0 = pk2(sv.x, sv.x);
                unsigned long long s1 = pk2(sv.y, sv.y);
                unsigned long long s2 = pk2(sv.z, sv.z);
                unsigned long long s3 = pk2(sv.w, sv.w);
                fma2(acc[r][0], s0, wp[0][0]); fma2(acc[r][1], s0, wp[0][1]);
                fma2(acc[r][0], s1, wp[1][0]); fma2(acc[r][1], s1, wp[1][1]);
                fma2(acc[r][0], s2, wp[2][0]); fma2(acc[r][1], s2, wp[2][1]);
                fma2(acc[r][0], s3, wp[3][0]); fma2(acc[r][1], s3, wp[3][1]);
            }
        }
    }

    // ---- epilogue ----
    int col = lane * 4;
#pragma unroll
    for (int r = 0; r < 8; r++) {
        int grow = row0 + rbase + r;
        if (grow >= NN) break;
        float4 o;
        upk2(acc[r][0], o.x, o.y);
        upk2(acc[r][1], o.z, o.w);
        float4 sv = *(const float4*)&ss[rbase + r][col];
        o.x = fmaf(cs, sv.x, o.x * cw);
        o.y = fmaf(cs, sv.y, o.y * cw);
        o.z = fmaf(cs, sv.z, o.z * cw);
        o.w = fmaf(cs, sv.w, o.w * cw);
        o.x = fmaxf(o.x, 0.f); o.y = fmaxf(o.y, 0.f);
        o.z = fmaxf(o.z, 0.f); o.w = fmaxf(o.w, 0.f);
        *(float4*)(out + (size_t)grow * HIDC + col) = o;
        if (out16) {
            uint2 hp;
            *(__half2*)&hp.x = __floats2half2_rn(o.x, o.y);
            *(__half2*)&hp.y = __floats2half2_rn(o.z, o.w);
            *(uint2*)(out16 + (size_t)grow * HIDC + col) = hp;
        }
    }
}

// ---------------- output projection ----------------
__global__ __launch_bounds__(256) void outproj_kernel(const float* __restrict__ h,
                                                      const float* __restrict__ Wout,
                                                      const float* __restrict__ bout,
                                                      float* __restrict__ out) {
    int warp = (blockIdx.x * blockDim.x + threadIdx.x) >> 5;
    if (warp >= NN) return;
    int lane = threadIdx.x & 31;
    float4 hv = *(const float4*)(h + (size_t)warp * HIDC + lane * 4);
    float4 wv = *(const float4*)(Wout + lane * 4);
    float a = hv.x * wv.x + hv.y * wv.y + hv.z * wv.z + hv.w * wv.w;
#pragma unroll
    for (int off = 16; off; off >>= 1) a += __shfl_xor_sync(0xffffffffu, a, off);
    if (lane == 0) out[warp] = a + bout[0];
}

// ---------------- launch ----------------
extern "C" void kernel_launch(void* const* d_in, const int* in_sizes, int n_in,
                              void* d_out, int out_size) {
    const float* x     = (const float*)d_in[0];
    const float* W_in  = (const float*)d_in[2];
    const float* b_in  = (const float*)d_in[3];
    const float* W_gcn = (const float*)d_in[4];
    const float* W_out = (const float*)d_in[5];
    const float* b_out = (const float*)d_in[6];
    const int*   ei    = (const int*)d_in[7];
    float* out = (float*)d_out;

    void *pDeg, *pH0, *pA, *pB, *pHa, *pHb;
    cudaGetSymbolAddress(&pDeg, g_deg);
    cudaGetSymbolAddress(&pH0,  g_h0);
    cudaGetSymbolAddress(&pA,   g_bufA);
    cudaGetSymbolAddress(&pB,   g_bufB);
    cudaGetSymbolAddress(&pHa,  g_h16a);
    cudaGetSymbolAddress(&pHb,  g_h16b);
    float*  h0   = (float*)pH0;
    float*  bufA = (float*)pA;
    float*  bufB = (float*)pB;
    __half* t16[2] = { (__half*)pHa, (__half*)pHb };

    // graph build
    detect_kernel<<<1, 32>>>(ei);
    cudaMemsetAsync(pDeg, 0, NN * sizeof(int), 0);
    count_kernel<<<EE / 256, 256>>>(ei);
    scan_kernel<<<1, 1024>>>();
    fill_kernel<<<EE / 256, 256>>>(ei);

    const int GB = NPAD / 64;   // 1563

    // input projection: h0 = x @ W_in + b_in (fp32 out + fp16 table A)
    gemm_kernel<<<GB, 256>>>(x, W_in, b_in, 0.f, 1.f, 0, h0, t16[0]);

    const float* cur = h0;
    for (int i = 0; i < 8; i++) {
        float beta = logf(0.5f / (float)(i + 1) + 1.0f);
        float* dst = (i & 1) ? bufB : bufA;
        __half* src16 = t16[i & 1];
        __half* dst16 = (i == 7) ? nullptr : t16[(i + 1) & 1];
        fused_kernel<<<GB, 256>>>(src16, cur, h0,
                                  W_gcn + (size_t)i * HIDC * HIDC,
                                  1.0f - beta, beta, dst, dst16);
        cur = dst;
    }

    outproj_kernel<<<NN / 8, 256>>>(cur, W_out, b_out, out);
}

// round 16
// speedup vs baseline: 2.0253x; 2.0253x over previous
#include <cuda_runtime.h>
#include <cuda_fp16.h>
#include <mma.h>
#include <math.h>

using namespace nvcuda;

#define NN 100000
#define NPAD 100032
#define EE 3200000
#define HIDC 128

// ---------------- device scratch (no allocations allowed) ----------------
__device__ int    g_flag64;
__device__ int    g_deg[NN];
__device__ float  g_dinv[NN];
__device__ int    g_rowptr[NN + 1];
__device__ int    g_cursor[NN];
__device__ int    g_src[EE];
__device__ float  g_w[EE];
__device__ float  g_h0[(size_t)NN * HIDC];
__device__ float  g_bufA[(size_t)NN * HIDC];
__device__ float  g_bufB[(size_t)NN * HIDC];
__device__ float  g_sbuf[(size_t)NN * HIDC];
__device__ __half g_h16[(size_t)NPAD * HIDC];     // fp16 h table (gather + GEMM-A for inproj)
__device__ __half g_sbuf16[(size_t)NPAD * HIDC];  // fp16 s table (GEMM-A)
__device__ __half g_w16[9 * HIDC * HIDC];         // fp16 weights: W_in, W_gcn[0..7]

// ---------------- dtype detection ----------------
__global__ void detect_kernel(const int* __restrict__ ew) {
    if (threadIdx.x == 0) {
        int allzero = 1;
        for (int i = 0; i < 256; i++) {
            if (ew[2 * i + 1] != 0) { allzero = 0; break; }
        }
        g_flag64 = allzero;
    }
}

__device__ __forceinline__ int load_idx(const int* __restrict__ ew, long long elem, int f64) {
    return f64 ? ew[2 * elem] : ew[elem];
}

// ---------------- graph build ----------------
__global__ void count_kernel(const int* __restrict__ ew) {
    int e = blockIdx.x * blockDim.x + threadIdx.x;
    if (e < EE) {
        int f64 = g_flag64;
        int c = load_idx(ew, (long long)EE + e, f64);
        if ((unsigned)c < NN) atomicAdd(&g_deg[c], 1);
    }
}

__global__ void scan_kernel() {
    __shared__ int sums[1024];
    const int T = 1024;
    int t = threadIdx.x;
    const int CH = (NN + T - 1) / T;
    int lo = t * CH;
    int hi = lo + CH;
    if (hi > NN) hi = NN;
    if (lo > NN) lo = NN;
    int s = 0;
    for (int i = lo; i < hi; i++) s += g_deg[i];
    sums[t] = s;
    __syncthreads();
    for (int off = 1; off < T; off <<= 1) {
        int v = (t >= off) ? sums[t - off] : 0;
        __syncthreads();
        sums[t] += v;
        __syncthreads();
    }
    int run = sums[t] - s;
    for (int i = lo; i < hi; i++) {
        int d = g_deg[i];
        g_rowptr[i] = run;
        g_cursor[i] = run;
        g_dinv[i]   = rsqrtf((float)(d + 1));
        run += d;
    }
    if (t == T - 1) g_rowptr[NN] = run;
}

__global__ void fill_kernel(const int* __restrict__ ew) {
    int e = blockIdx.x * blockDim.x + threadIdx.x;
    if (e < EE) {
        int f64 = g_flag64;
        int r = load_idx(ew, e, f64);
        int c = load_idx(ew, (long long)EE + e, f64);
        if ((unsigned)r < NN && (unsigned)c < NN) {
            int pos = atomicAdd(&g_cursor[c], 1);
            g_src[pos] = r;
            g_w[pos]   = g_dinv[r] * g_dinv[c];
        }
    }
}

// ---------------- fp16 conversions ----------------
__global__ void convw_kernel(const float* __restrict__ Win,
                             const float* __restrict__ Wgcn) {
    int i = blockIdx.x * blockDim.x + threadIdx.x;
    if (i < 9 * HIDC * HIDC) {
        float v = (i < HIDC * HIDC) ? Win[i] : Wgcn[i - HIDC * HIDC];
        g_w16[i] = __float2half_rn(v);
    }
}

__global__ void convx_kernel(const float* __restrict__ x) {
    int i = blockIdx.x * blockDim.x + threadIdx.x;   // quads
    if (i < NN * HIDC / 4) {
        float4 v = ((const float4*)x)[i];
        uint2 p;
        *(__half2*)&p.x = __floats2half2_rn(v.x, v.y);
        *(__half2*)&p.y = __floats2half2_rn(v.z, v.w);
        *(uint2*)(&g_h16[(size_t)i * 4]) = p;
    }
}

// ---------------- SpMM + residual: s = 0.9*(A_norm h) + 0.1*h0 ----------------
__global__ __launch_bounds__(256) void spmm_kernel(const __half* __restrict__ h16,
                                                   const float* __restrict__ hf,
                                                   const float* __restrict__ h0f,
                                                   float* __restrict__ sout,
                                                   __half* __restrict__ sout16) {
    int warp = (blockIdx.x * blockDim.x + threadIdx.x) >> 5;
    if (warp >= NN) return;
    int lane = threadIdx.x & 31;
    int beg = g_rowptr[warp];
    int end = g_rowptr[warp + 1];

    float4 acc = make_float4(0.f, 0.f, 0.f, 0.f);
    int e0 = beg;
    for (; e0 + 32 <= end; e0 += 32) {
        int   src = g_src[e0 + lane];
        float w   = g_w[e0 + lane];
#pragma unroll 8
        for (int j = 0; j < 32; j++) {
            int   sidx = __shfl_sync(0xffffffffu, src, j);
            float ww   = __shfl_sync(0xffffffffu, w, j);
            uint2 rv = *(const uint2*)(h16 + (size_t)sidx * HIDC + lane * 4);
            float2 f0 = __half22float2(*(const __half2*)&rv.x);
            float2 f1 = __half22float2(*(const __half2*)&rv.y);
            acc.x = fmaf(ww, f0.x, acc.x);
            acc.y = fmaf(ww, f0.y, acc.y);
            acc.z = fmaf(ww, f1.x, acc.z);
            acc.w = fmaf(ww, f1.y, acc.w);
        }
    }
    if (e0 < end) {
        int cnt = end - e0;
        int   src = 0;
        float w   = 0.f;
        if (lane < cnt) { src = g_src[e0 + lane]; w = g_w[e0 + lane]; }
        for (int j = 0; j < cnt; j++) {
            int   sidx = __shfl_sync(0xffffffffu, src, j);
            float ww   = __shfl_sync(0xffffffffu, w, j);
            uint2 rv = *(const uint2*)(h16 + (size_t)sidx * HIDC + lane * 4);
            float2 f0 = __half22float2(*(const __half2*)&rv.x);
            float2 f1 = __half22float2(*(const __half2*)&rv.y);
            acc.x = fmaf(ww, f0.x, acc.x);
            acc.y = fmaf(ww, f0.y, acc.y);
            acc.z = fmaf(ww, f1.x, acc.z);
            acc.w = fmaf(ww, f1.y, acc.w);
        }
    }
    // self loop in fp32
    float di = g_dinv[warp];
    float ws = di * di;
    float4 hv = *(const float4*)(hf + (size_t)warp * HIDC + lane * 4);
    acc.x = fmaf(ws, hv.x, acc.x);
    acc.y = fmaf(ws, hv.y, acc.y);
    acc.z = fmaf(ws, hv.z, acc.z);
    acc.w = fmaf(ws, hv.w, acc.w);

    float4 r0 = *(const float4*)(h0f + (size_t)warp * HIDC + lane * 4);
    float4 o;
    o.x = 0.9f * acc.x + 0.1f * r0.x;
    o.y = 0.9f * acc.y + 0.1f * r0.y;
    o.z = 0.9f * acc.z + 0.1f * r0.z;
    o.w = 0.9f * acc.w + 0.1f * r0.w;
    *(float4*)(sout + (size_t)warp * HIDC + lane * 4) = o;
    uint2 hp;
    *(__half2*)&hp.x = __floats2half2_rn(o.x, o.y);
    *(__half2*)&hp.y = __floats2half2_rn(o.z, o.w);
    *(uint2*)(sout16 + (size_t)warp * HIDC + lane * 4) = hp;
}

// ---------------- HMMA GEMM (smem-staged): out = cs*Sf + cw*(A16@W16) ----------------
// 64x128 tile, 8 warps (4m x 2n), wmma fragments loaded from smem (LDSM).
// smem: A 64x128 fp16 (stride 136) + W chunk 64x128 fp16 (stride 136); C overlays.
#define SLD 136
__global__ __launch_bounds__(256) void mma_gemm_kernel(const __half* __restrict__ A16,
                                                       const float* __restrict__ Sf,
                                                       const __half* __restrict__ W16,
                                                       const float* __restrict__ bias,
                                                       float cs, float cw, int relu,
                                                       float* __restrict__ out,
                                                       __half* __restrict__ out16) {
    __shared__ __align__(16) char smemBuf[64 * SLD * 2 + 64 * SLD * 2];  // 34816 B
    __half* sA = (__half*)smemBuf;                    // 64 x SLD halves
    __half* sB = (__half*)(smemBuf + 64 * SLD * 2);   // 64 x SLD halves (W k-chunk)
    float*  sC = (float*)smemBuf;                     // 64 x 128 fp32 (overlay)

    int tid  = threadIdx.x;
    int warp = tid >> 5;
    int lane = tid & 31;
    int mw = warp & 3;          // 16-row group
    int nw = warp >> 2;         // 64-col group
    int row0 = blockIdx.x * 64;

    // load A tile: 64 rows x 16 chunks(8 halves)
#pragma unroll
    for (int i = 0; i < 4; i++) {
        int idx = tid + i * 256;          // 0..1023
        int r = idx >> 4, c = idx & 15;
        *(uint4*)&sA[r * SLD + c * 8] =
            *(const uint4*)(A16 + (size_t)(row0 + r) * HIDC + c * 8);
    }

    wmma::fragment<wmma::accumulator, 16, 16, 16, float> c[4];
#pragma unroll
    for (int j = 0; j < 4; j++) wmma::fill_fragment(c[j], 0.f);

#pragma unroll
    for (int kc = 0; kc < 2; kc++) {
        __syncthreads();  // first: covers sA writes; second: guards sB reuse
        // load W rows kc*64..+64
#pragma unroll
        for (int i = 0; i < 4; i++) {
            int idx = tid + i * 256;
            int r = idx >> 4, cc = idx & 15;
            *(uint4*)&sB[r * SLD + cc * 8] =
                *(const uint4*)(W16 + (size_t)(kc * 64 + r) * HIDC + cc * 8);
        }
        __syncthreads();
#pragma unroll
        for (int k = 0; k < 4; k++) {
            wmma::fragment<wmma::matrix_a, 16, 16, 16, __half, wmma::row_major> a;
            wmma::load_matrix_sync(a, sA + (mw * 16) * SLD + kc * 64 + k * 16, SLD);
#pragma unroll
            for (int j = 0; j < 4; j++) {
                wmma::fragment<wmma::matrix_b, 16, 16, 16, __half, wmma::row_major> b;
                wmma::load_matrix_sync(b, sB + (k * 16) * SLD + nw * 64 + j * 16, SLD);
                wmma::mma_sync(c[j], a, b, c[j]);
            }
        }
    }

    __syncthreads();   // all mma reads done before C overlays A/B
#pragma unroll
    for (int j = 0; j < 4; j++)
        wmma::store_matrix_sync(&sC[(mw * 16) * 128 + nw * 64 + j * 16], c[j], 128,
                                wmma::mem_row_major);
    __syncthreads();

    // epilogue: thread = 8 rows x 4 cols
    int rbase = warp * 8;
    int col   = lane * 4;
    float4 b4 = make_float4(0.f, 0.f, 0.f, 0.f);
    if (bias) b4 = *(const float4*)(bias + col);

#pragma unroll
    for (int r = 0; r < 8; r++) {
        int grow = row0 + rbase + r;
        if (grow >= NN) break;
        float4 o = *(float4*)&sC[(rbase + r) * 128 + col];
        o.x *= cw; o.y *= cw; o.z *= cw; o.w *= cw;
        if (cs != 0.f) {
            float4 sv = *(const float4*)(Sf + (size_t)grow * HIDC + col);
            o.x = fmaf(cs, sv.x, o.x);
            o.y = fmaf(cs, sv.y, o.y);
            o.z = fmaf(cs, sv.z, o.z);
            o.w = fmaf(cs, sv.w, o.w);
        }
        o.x += b4.x; o.y += b4.y; o.z += b4.z; o.w += b4.w;
        if (relu) {
            o.x = fmaxf(o.x, 0.f); o.y = fmaxf(o.y, 0.f);
            o.z = fmaxf(o.z, 0.f); o.w = fmaxf(o.w, 0.f);
        }
        *(float4*)(out + (size_t)grow * HIDC + col) = o;
        if (out16) {
            uint2 hp;
            *(__half2*)&hp.x = __floats2half2_rn(o.x, o.y);
            *(__half2*)&hp.y = __floats2half2_rn(o.z, o.w);
            *(uint2*)(out16 + (size_t)grow * HIDC + col) = hp;
        }
    }
}

// ---------------- output projection ----------------
__global__ __launch_bounds__(256) void outproj_kernel(const float* __restrict__ h,
                                                      const float* __restrict__ Wout,
                                                      const float* __restrict__ bout,
                                                      float* __restrict__ out) {
    int warp = (blockIdx.x * blockDim.x + threadIdx.x) >> 5;
    if (warp >= NN) return;
    int lane = threadIdx.x & 31;
    float4 hv = *(const float4*)(h + (size_t)warp * HIDC + lane * 4);
    float4 wv = *(const float4*)(Wout + lane * 4);
    float a = hv.x * wv.x + hv.y * wv.y + hv.z * wv.z + hv.w * wv.w;
#pragma unroll
    for (int off = 16; off; off >>= 1) a += __shfl_xor_sync(0xffffffffu, a, off);
    if (lane == 0) out[warp] = a + bout[0];
}

// ---------------- launch ----------------
extern "C" void kernel_launch(void* const* d_in, const int* in_sizes, int n_in,
                              void* d_out, int out_size) {
    const float* x     = (const float*)d_in[0];
    const float* W_in  = (const float*)d_in[2];
    const float* b_in  = (const float*)d_in[3];
    const float* W_gcn = (const float*)d_in[4];
    const float* W_out = (const float*)d_in[5];
    const float* b_out = (const float*)d_in[6];
    const int*   ei    = (const int*)d_in[7];
    float* out = (float*)d_out;

    void *pDeg, *pH0, *pA, *pB, *pS, *pH16, *pS16, *pW16;
    cudaGetSymbolAddress(&pDeg, g_deg);
    cudaGetSymbolAddress(&pH0,  g_h0);
    cudaGetSymbolAddress(&pA,   g_bufA);
    cudaGetSymbolAddress(&pB,   g_bufB);
    cudaGetSymbolAddress(&pS,   g_sbuf);
    cudaGetSymbolAddress(&pH16, g_h16);
    cudaGetSymbolAddress(&pS16, g_sbuf16);
    cudaGetSymbolAddress(&pW16, g_w16);
    float*  h0   = (float*)pH0;
    float*  bufA = (float*)pA;
    float*  bufB = (float*)pB;
    float*  sbuf = (float*)pS;
    __half* h16  = (__half*)pH16;
    __half* s16  = (__half*)pS16;
    __half* w16  = (__half*)pW16;

    // graph build
    detect_kernel<<<1, 32>>>(ei);
    cudaMemsetAsync(pDeg, 0, NN * sizeof(int), 0);
    count_kernel<<<EE / 256, 256>>>(ei);
    scan_kernel<<<1, 1024>>>();
    fill_kernel<<<EE / 256, 256>>>(ei);

    // fp16 conversions
    convw_kernel<<<(9 * HIDC * HIDC + 255) / 256, 256>>>(W_in, W_gcn);
    convx_kernel<<<(NN * HIDC / 4 + 255) / 256, 256>>>(x);

    const int GB = NPAD / 64;   // 1563

    // input projection: h0 = x16 @ W_in16 + b_in  (writes fp32 h0 + fp16 table)
    mma_gemm_kernel<<<GB, 256>>>(h16, nullptr, w16, b_in, 0.f, 1.f, 0, h0, h16);

    const float* cur = h0;
    for (int i = 0; i < 8; i++) {
        spmm_kernel<<<NN / 8, 256>>>(h16, cur, h0, sbuf, s16);
        float beta = logf(0.5f / (float)(i + 1) + 1.0f);
        float* dst = (i & 1) ? bufB : bufA;
        __half* t16 = (i == 7) ? nullptr : h16;
        mma_gemm_kernel<<<GB, 256>>>(s16, sbuf, w16 + (size_t)(i + 1) * HIDC * HIDC,
                                     nullptr, 1.0f - beta, beta, 1, dst, t16);
        cur = dst;
    }

    outproj_kernel<<<NN / 8, 256>>>(cur, W_out, b_out, out);
}

// round 17
// speedup vs baseline: 2.2710x; 1.1213x over previous
#include <cuda_runtime.h>
#include <cuda_fp16.h>
#include <mma.h>
#include <math.h>

using namespace nvcuda;

#define NN 100000
#define NPAD 100032
#define EE 3200000
#define HIDC 128

// ---------------- device scratch (no allocations allowed) ----------------
__device__ int    g_flag64;
__device__ int    g_deg[NN];
__device__ float  g_dinv[NN];
__device__ int    g_rowptr[NN + 1];
__device__ int    g_cursor[NN];
__device__ int    g_src[EE];
__device__ float  g_w[EE];
__device__ float  g_final[(size_t)NN * HIDC];     // fp32 final h (outproj input)
__device__ __half g_h16[(size_t)NPAD * HIDC];     // fp16 current-h table
__device__ __half g_h016[(size_t)NPAD * HIDC];    // fp16 h0 residual table
__device__ __half g_sbuf16[(size_t)NPAD * HIDC];  // fp16 s table (GEMM-A)
__device__ __half g_w16[9 * HIDC * HIDC];         // fp16 weights: W_in, W_gcn[0..7]

// ---------------- dtype detection ----------------
__global__ void detect_kernel(const int* __restrict__ ew) {
    if (threadIdx.x == 0) {
        int allzero = 1;
        for (int i = 0; i < 256; i++) {
            if (ew[2 * i + 1] != 0) { allzero = 0; break; }
        }
        g_flag64 = allzero;
    }
}

__device__ __forceinline__ int load_idx(const int* __restrict__ ew, long long elem, int f64) {
    return f64 ? ew[2 * elem] : ew[elem];
}

// ---------------- graph build ----------------
__global__ void count_kernel(const int* __restrict__ ew) {
    int e = blockIdx.x * blockDim.x + threadIdx.x;
    if (e < EE) {
        int f64 = g_flag64;
        int c = load_idx(ew, (long long)EE + e, f64);
        if ((unsigned)c < NN) atomicAdd(&g_deg[c], 1);
    }
}

__global__ void scan_kernel() {
    __shared__ int sums[1024];
    const int T = 1024;
    int t = threadIdx.x;
    const int CH = (NN + T - 1) / T;
    int lo = t * CH;
    int hi = lo + CH;
    if (hi > NN) hi = NN;
    if (lo > NN) lo = NN;
    int s = 0;
    for (int i = lo; i < hi; i++) s += g_deg[i];
    sums[t] = s;
    __syncthreads();
    for (int off = 1; off < T; off <<= 1) {
        int v = (t >= off) ? sums[t - off] : 0;
        __syncthreads();
        sums[t] += v;
        __syncthreads();
    }
    int run = sums[t] - s;
    for (int i = lo; i < hi; i++) {
        int d = g_deg[i];
        g_rowptr[i] = run;
        g_cursor[i] = run;
        g_dinv[i]   = rsqrtf((float)(d + 1));
        run += d;
    }
    if (t == T - 1) g_rowptr[NN] = run;
}

__global__ void fill_kernel(const int* __restrict__ ew) {
    int e = blockIdx.x * blockDim.x + threadIdx.x;
    if (e < EE) {
        int f64 = g_flag64;
        int r = load_idx(ew, e, f64);
        int c = load_idx(ew, (long long)EE + e, f64);
        if ((unsigned)r < NN && (unsigned)c < NN) {
            int pos = atomicAdd(&g_cursor[c], 1);
            g_src[pos] = r;
            g_w[pos]   = g_dinv[r] * g_dinv[c];
        }
    }
}

// ---------------- fp16 conversions ----------------
__global__ void convw_kernel(const float* __restrict__ Win,
                             const float* __restrict__ Wgcn) {
    int i = blockIdx.x * blockDim.x + threadIdx.x;
    if (i < 9 * HIDC * HIDC) {
        float v = (i < HIDC * HIDC) ? Win[i] : Wgcn[i - HIDC * HIDC];
        g_w16[i] = __float2half_rn(v);
    }
}

__global__ void convx_kernel(const float* __restrict__ x) {
    int i = blockIdx.x * blockDim.x + threadIdx.x;   // quads
    if (i < NN * HIDC / 4) {
        float4 v = ((const float4*)x)[i];
        uint2 p;
        *(__half2*)&p.x = __floats2half2_rn(v.x, v.y);
        *(__half2*)&p.y = __floats2half2_rn(v.z, v.w);
        *(uint2*)(&g_sbuf16[(size_t)i * 4]) = p;   // x16 staged as GEMM-A for inproj
    }
}

// ---------------- SpMM + residual (all fp16 I/O, fp32 accumulate) ----------------
// s16 = fp16( 0.9*(A_norm h16) + 0.1*h016 )
__global__ __launch_bounds__(256) void spmm_kernel(const __half* __restrict__ h16,
                                                   const __half* __restrict__ h016,
                                                   __half* __restrict__ sout16) {
    int warp = (blockIdx.x * blockDim.x + threadIdx.x) >> 5;
    if (warp >= NN) return;
    int lane = threadIdx.x & 31;
    int beg = g_rowptr[warp];
    int end = g_rowptr[warp + 1];

    float4 acc = make_float4(0.f, 0.f, 0.f, 0.f);
    int e0 = beg;
    for (; e0 + 32 <= end; e0 += 32) {
        int   src = g_src[e0 + lane];
        float w   = g_w[e0 + lane];
#pragma unroll 8
        for (int j = 0; j < 32; j++) {
            int   sidx = __shfl_sync(0xffffffffu, src, j);
            float ww   = __shfl_sync(0xffffffffu, w, j);
            uint2 rv = *(const uint2*)(h16 + (size_t)sidx * HIDC + lane * 4);
            float2 f0 = __half22float2(*(const __half2*)&rv.x);
            float2 f1 = __half22float2(*(const __half2*)&rv.y);
            acc.x = fmaf(ww, f0.x, acc.x);
            acc.y = fmaf(ww, f0.y, acc.y);
            acc.z = fmaf(ww, f1.x, acc.z);
            acc.w = fmaf(ww, f1.y, acc.w);
        }
    }
    if (e0 < end) {
        int cnt = end - e0;
        int   src = 0;
        float w   = 0.f;
        if (lane < cnt) { src = g_src[e0 + lane]; w = g_w[e0 + lane]; }
        for (int j = 0; j < cnt; j++) {
            int   sidx = __shfl_sync(0xffffffffu, src, j);
            float ww   = __shfl_sync(0xffffffffu, w, j);
            uint2 rv = *(const uint2*)(h16 + (size_t)sidx * HIDC + lane * 4);
            float2 f0 = __half22float2(*(const __half2*)&rv.x);
            float2 f1 = __half22float2(*(const __half2*)&rv.y);
            acc.x = fmaf(ww, f0.x, acc.x);
            acc.y = fmaf(ww, f0.y, acc.y);
            acc.z = fmaf(ww, f1.x, acc.z);
            acc.w = fmaf(ww, f1.y, acc.w);
        }
    }
    // self loop from own fp16 row (L2-hot)
    float di = g_dinv[warp];
    float ws = di * di;
    {
        uint2 rv = *(const uint2*)(h16 + (size_t)warp * HIDC + lane * 4);
        float2 f0 = __half22float2(*(const __half2*)&rv.x);
        float2 f1 = __half22float2(*(const __half2*)&rv.y);
        acc.x = fmaf(ws, f0.x, acc.x);
        acc.y = fmaf(ws, f0.y, acc.y);
        acc.z = fmaf(ws, f1.x, acc.z);
        acc.w = fmaf(ws, f1.y, acc.w);
    }
    // residual from fp16 h0 table
    float4 r0;
    {
        uint2 rv = *(const uint2*)(h016 + (size_t)warp * HIDC + lane * 4);
        float2 f0 = __half22float2(*(const __half2*)&rv.x);
        float2 f1 = __half22float2(*(const __half2*)&rv.y);
        r0 = make_float4(f0.x, f0.y, f1.x, f1.y);
    }
    float4 o;
    o.x = 0.9f * acc.x + 0.1f * r0.x;
    o.y = 0.9f * acc.y + 0.1f * r0.y;
    o.z = 0.9f * acc.z + 0.1f * r0.z;
    o.w = 0.9f * acc.w + 0.1f * r0.w;
    uint2 hp;
    *(__half2*)&hp.x = __floats2half2_rn(o.x, o.y);
    *(__half2*)&hp.y = __floats2half2_rn(o.z, o.w);
    *(uint2*)(sout16 + (size_t)warp * HIDC + lane * 4) = hp;
}

// ---------------- HMMA GEMM (smem-staged): o = cs*A + cw*(A@W) (+bias)(relu) ----------------
// 64x128 tile, 8 warps (4m x 2n). Pass-through A term snapshot from smem sA.
// Outputs optional: fp32 out32, fp16 out16 (+duplicate out16b).
#define SLD 136
__global__ __launch_bounds__(256) void mma_gemm_kernel(const __half* __restrict__ A16,
                                                       const __half* __restrict__ W16,
                                                       const float* __restrict__ bias,
                                                       float cs, float cw, int relu,
                                                       float* __restrict__ out32,
                                                       __half* __restrict__ out16,
                                                       __half* __restrict__ out16b) {
    __shared__ __align__(16) char smemBuf[64 * SLD * 2 + 64 * SLD * 2];  // 34816 B
    __half* sA = (__half*)smemBuf;                    // 64 x SLD halves
    __half* sB = (__half*)(smemBuf + 64 * SLD * 2);   // 64 x SLD halves
    float*  sC = (float*)smemBuf;                     // 64 x 128 fp32 (overlay)

    int tid  = threadIdx.x;
    int warp = tid >> 5;
    int lane = tid & 31;
    int mw = warp & 3;
    int nw = warp >> 2;
    int row0 = blockIdx.x * 64;

    // load A tile
#pragma unroll
    for (int i = 0; i < 4; i++) {
        int idx = tid + i * 256;
        int r = idx >> 4, c = idx & 15;
        *(uint4*)&sA[r * SLD + c * 8] =
            *(const uint4*)(A16 + (size_t)(row0 + r) * HIDC + c * 8);
    }

    wmma::fragment<wmma::accumulator, 16, 16, 16, float> c[4];
#pragma unroll
    for (int j = 0; j < 4; j++) wmma::fill_fragment(c[j], 0.f);

#pragma unroll
    for (int kc = 0; kc < 2; kc++) {
        __syncthreads();
#pragma unroll
        for (int i = 0; i < 4; i++) {
            int idx = tid + i * 256;
            int r = idx >> 4, cc = idx & 15;
            *(uint4*)&sB[r * SLD + cc * 8] =
                *(const uint4*)(W16 + (size_t)(kc * 64 + r) * HIDC + cc * 8);
        }
        __syncthreads();
#pragma unroll
        for (int k = 0; k < 4; k++) {
            wmma::fragment<wmma::matrix_a, 16, 16, 16, __half, wmma::row_major> a;
            wmma::load_matrix_sync(a, sA + (mw * 16) * SLD + kc * 64 + k * 16, SLD);
#pragma unroll
            for (int j = 0; j < 4; j++) {
                wmma::fragment<wmma::matrix_b, 16, 16, 16, __half, wmma::row_major> b;
                wmma::load_matrix_sync(b, sB + (k * 16) * SLD + nw * 64 + j * 16, SLD);
                wmma::mma_sync(c[j], a, b, c[j]);
            }
        }
    }

    __syncthreads();   // mma reads done

    // snapshot pass-through A values (this thread's 8 rows x 4 cols) before C overlay
    int rbase = warp * 8;
    int col   = lane * 4;
    float4 pass[8];
#pragma unroll
    for (int r = 0; r < 8; r++) {
        uint2 rv = *(uint2*)&sA[(rbase + r) * SLD + col];
        float2 f0 = __half22float2(*(const __half2*)&rv.x);
        float2 f1 = __half22float2(*(const __half2*)&rv.y);
        pass[r] = make_float4(f0.x, f0.y, f1.x, f1.y);
    }
    __syncthreads();

#pragma unroll
    for (int j = 0; j < 4; j++)
        wmma::store_matrix_sync(&sC[(mw * 16) * 128 + nw * 64 + j * 16], c[j], 128,
                                wmma::mem_row_major);
    __syncthreads();

    float4 b4 = make_float4(0.f, 0.f, 0.f, 0.f);
    if (bias) b4 = *(const float4*)(bias + col);

#pragma unroll
    for (int r = 0; r < 8; r++) {
        int grow = row0 + rbase + r;
        if (grow >= NN) break;
        float4 o = *(float4*)&sC[(rbase + r) * 128 + col];
        o.x = fmaf(cs, pass[r].x, o.x * cw) + b4.x;
        o.y = fmaf(cs, pass[r].y, o.y * cw) + b4.y;
        o.z = fmaf(cs, pass[r].z, o.z * cw) + b4.z;
        o.w = fmaf(cs, pass[r].w, o.w * cw) + b4.w;
        if (relu) {
            o.x = fmaxf(o.x, 0.f); o.y = fmaxf(o.y, 0.f);
            o.z = fmaxf(o.z, 0.f); o.w = fmaxf(o.w, 0.f);
        }
        if (out32)
            *(float4*)(out32 + (size_t)grow * HIDC + col) = o;
        if (out16) {
            uint2 hp;
            *(__half2*)&hp.x = __floats2half2_rn(o.x, o.y);
            *(__half2*)&hp.y = __floats2half2_rn(o.z, o.w);
            *(uint2*)(out16 + (size_t)grow * HIDC + col) = hp;
            if (out16b)
                *(uint2*)(out16b + (size_t)grow * HIDC + col) = hp;
        }
    }
}

// ---------------- output projection ----------------
__global__ __launch_bounds__(256) void outproj_kernel(const float* __restrict__ h,
                                                      const float* __restrict__ Wout,
                                                      const float* __restrict__ bout,
                                                      float* __restrict__ out) {
    int warp = (blockIdx.x * blockDim.x + threadIdx.x) >> 5;
    if (warp >= NN) return;
    int lane = threadIdx.x & 31;
    float4 hv = *(const float4*)(h + (size_t)warp * HIDC + lane * 4);
    float4 wv = *(const float4*)(Wout + lane * 4);
    float a = hv.x * wv.x + hv.y * wv.y + hv.z * wv.z + hv.w * wv.w;
#pragma unroll
    for (int off = 16; off; off >>= 1) a += __shfl_xor_sync(0xffffffffu, a, off);
    if (lane == 0) out[warp] = a + bout[0];
}

// ---------------- launch ----------------
extern "C" void kernel_launch(void* const* d_in, const int* in_sizes, int n_in,
                              void* d_out, int out_size) {
    const float* x     = (const float*)d_in[0];
    const float* W_in  = (const float*)d_in[2];
    const float* b_in  = (const float*)d_in[3];
    const float* W_gcn = (const float*)d_in[4];
    const float* W_out = (const float*)d_in[5];
    const float* b_out = (const float*)d_in[6];
    const int*   ei    = (const int*)d_in[7];
    float* out = (float*)d_out;

    void *pDeg, *pF, *pH16, *pH016, *pS16, *pW16;
    cudaGetSymbolAddress(&pDeg,  g_deg);
    cudaGetSymbolAddress(&pF,    g_final);
    cudaGetSymbolAddress(&pH16,  g_h16);
    cudaGetSymbolAddress(&pH016, g_h016);
    cudaGetSymbolAddress(&pS16,  g_sbuf16);
    cudaGetSymbolAddress(&pW16,  g_w16);
    float*  fin  = (float*)pF;
    __half* h16  = (__half*)pH16;
    __half* h016 = (__half*)pH016;
    __half* s16  = (__half*)pS16;
    __half* w16  = (__half*)pW16;

    // graph build
    detect_kernel<<<1, 32>>>(ei);
    cudaMemsetAsync(pDeg, 0, NN * sizeof(int), 0);
    count_kernel<<<EE / 256, 256>>>(ei);
    scan_kernel<<<1, 1024>>>();
    fill_kernel<<<EE / 256, 256>>>(ei);

    // fp16 conversions (x16 staged into s16 as GEMM-A input)
    convw_kernel<<<(9 * HIDC * HIDC + 255) / 256, 256>>>(W_in, W_gcn);
    convx_kernel<<<(NN * HIDC / 4 + 255) / 256, 256>>>(x);

    const int GB = NPAD / 64;   // 1563

    // input projection: h0 = x16 @ W_in16 + b_in -> h16 + h016 tables (fp16 only)
    mma_gemm_kernel<<<GB, 256>>>(s16, w16, b_in, 0.f, 1.f, 0,
                                 nullptr, h16, h016);

    for (int i = 0; i < 8; i++) {
        spmm_kernel<<<NN / 8, 256>>>(h16, h016, s16);
        float beta = logf(0.5f / (float)(i + 1) + 1.0f);
        float*  o32 = (i == 7) ? fin : nullptr;
        __half* o16 = (i == 7) ? nullptr : h16;
        mma_gemm_kernel<<<GB, 256>>>(s16, w16 + (size_t)(i + 1) * HIDC * HIDC,
                                     nullptr, 1.0f - beta, beta, 1,
                                     o32, o16, nullptr);
    }

    outproj_kernel<<<NN / 8, 256>>>(fin, W_out, b_out, out);
}